// round 14
// baseline (speedup 1.0000x reference)
#include <cuda_runtime.h>
#include <cstdint>

constexpr int Bn = 4, Sn = 2048, Dn = 1024, Hn = 16, HSn = 64;

// Scratch (tf32 bit patterns)
__device__ uint32_t g_q[Bn * Hn * Sn * HSn];
__device__ uint32_t g_k[Bn * Hn * Sn * HSn];
__device__ uint32_t g_v[Bn * Hn * Sn * HSn];
__device__ uint32_t g_attn[Bn * Sn * Dn];
// Fragment-ordered operand buffers (layouts documented in R12):
__device__ uint4 g_xt2[64 * 64 * 512];
__device__ uint4 g_wt2[24 * 64 * 512];
__device__ uint4 g_at2[64 * 64 * 512];
__device__ uint4 g_wo2[8 * 64 * 512];
__device__ uint4 g_kf[64 * 64 * 512];
__device__ uint4 g_vf[64 * 64 * 512];

__device__ __forceinline__ uint32_t f2tf(float x) {
    uint32_t r; asm("cvt.rna.tf32.f32 %0, %1;" : "=r"(r) : "f"(x)); return r;
}
__device__ __forceinline__ void mma_tf32(float c[4], uint32_t a0, uint32_t a1,
                                         uint32_t a2, uint32_t a3, uint32_t b0, uint32_t b1) {
    asm volatile("mma.sync.aligned.m16n8k8.row.col.f32.tf32.tf32.f32 "
        "{%0,%1,%2,%3}, {%4,%5,%6,%7}, {%8,%9}, {%0,%1,%2,%3};\n"
        : "+f"(c[0]), "+f"(c[1]), "+f"(c[2]), "+f"(c[3])
        : "r"(a0), "r"(a1), "r"(a2), "r"(a3), "r"(b0), "r"(b1));
}
__device__ __forceinline__ void cp16(void* s, const void* g) {
    uint32_t d = (uint32_t)__cvta_generic_to_shared(s);
    asm volatile("cp.async.ca.shared.global [%0], [%1], 16;\n" :: "r"(d), "l"(g));
}
#define CP_COMMIT() asm volatile("cp.async.commit_group;\n" ::: "memory")
#define CP_WAIT0()  asm volatile("cp.async.wait_group 0;\n" ::: "memory")
#define CP_WAIT1()  asm volatile("cp.async.wait_group 1;\n" ::: "memory")

// ---------------------------------------------------------------------------
// Kernel 0: fused prep — X->A-frags, Wq/Wk/Wv->B-frags, Wo->B-frags
// ---------------------------------------------------------------------------
constexpr int NXF = 64 * 64 * 512;
constexpr int NWF = 24 * 64 * 512;
constexpr int NOF = 8 * 64 * 512;

__global__ __launch_bounds__(256) void cvt_all(
    const float* __restrict__ X,  const float* __restrict__ Wq,
    const float* __restrict__ Wk, const float* __restrict__ Wv,
    const float* __restrict__ Wo)
{
    const int total = NXF + NWF + NOF;
    int i = blockIdx.x * blockDim.x + threadIdx.x;
    for (; i < total; i += gridDim.x * blockDim.x) {
        if (i < NXF) {
            const int lane = i & 31, frag = (i >> 5) & 15, kc = (i >> 9) & 63, mblk = i >> 15;
            const int ks = frag & 1, mt = (frag >> 1) & 1, wm = frag >> 2;
            const int g = lane >> 2, t4 = lane & 3;
            const int r0 = mblk * 128 + wm * 32 + mt * 16 + g;
            const int k0 = kc * 16 + ks * 8 + t4;
            const float* p = X + (size_t)r0 * Dn + k0;
            g_xt2[i] = make_uint4(f2tf(p[0]), f2tf(p[8 * Dn]), f2tf(p[4]), f2tf(p[8 * Dn + 4]));
        } else if (i < NXF + NWF) {
            const int j = i - NXF;
            const int lane = j & 31, frag = (j >> 5) & 15, kc = (j >> 9) & 63, blk = j >> 15;
            const int which = blk >> 3, nb = blk & 7;
            const int nt = frag & 7, wn = frag >> 3;
            const int g = lane >> 2, t4 = lane & 3;
            const int n_local = wn * 64 + nt * 8 + g;
            const int head = nb * 2 + (n_local >= 64 ? 1 : 0);
            const int e = n_local & 63;
            const float* W = (which == 0) ? Wq : (which == 1) ? Wk : Wv;
            const float* p = W + ((size_t)head * Dn + kc * 16) * HSn + e;
            g_wt2[j] = make_uint4(f2tf(p[(size_t)t4 * HSn]), f2tf(p[(size_t)(t4 + 4) * HSn]),
                                  f2tf(p[(size_t)(8 + t4) * HSn]), f2tf(p[(size_t)(12 + t4) * HSn]));
        } else {
            const int j = i - NXF - NWF;
            const int lane = j & 31, frag = (j >> 5) & 15, kc = (j >> 9) & 63, nblk = j >> 15;
            const int nt = frag & 7, wn = frag >> 3;
            const int g = lane >> 2, t4 = lane & 3;
            const int n = nblk * 128 + wn * 64 + nt * 8 + g;
            const int k0 = kc * 16 + t4;
            const float* p = Wo + (size_t)k0 * Dn + n;
            g_wo2[j] = make_uint4(f2tf(p[0]), f2tf(p[4 * Dn]), f2tf(p[8 * Dn]), f2tf(p[12 * Dn]));
        }
    }
}

// ---------------------------------------------------------------------------
// Kernel P1: K,V -> attn B-frags (g_kf, g_vf)
// ---------------------------------------------------------------------------
__global__ __launch_bounds__(256) void perm_kv()
{
    const int total = 64 * 64 * 512;
    int i = blockIdx.x * blockDim.x + threadIdx.x;
    for (; i < 2 * total; i += gridDim.x * blockDim.x) {
        const bool isV = i >= total;
        const int j = isV ? i - total : i;
        const int lane = j & 31, frag = (j >> 5) & 15, jt = (j >> 9) & 63, bh = j >> 15;
        const int g = lane >> 2, t4 = lane & 3;
        if (!isV) {
            const int nt = frag >> 2, kp = frag & 3;
            const int n = jt * 32 + nt * 8 + g;
            const uint32_t* p = g_k + ((size_t)bh * Sn + n) * HSn + kp * 16 + t4;
            g_kf[j] = make_uint4(p[0], p[4], p[8], p[12]);
        } else {
            const int nt = frag >> 1, kp = frag & 1;
            const int hs = nt * 8 + g;
            const int k0 = jt * 32 + kp * 16 + t4;
            const uint32_t* p = g_v + ((size_t)bh * Sn + k0) * HSn + hs;
            g_vf[j] = make_uint4(p[0], p[4 * HSn], p[8 * HSn], p[12 * HSn]);
        }
    }
}

// ---------------------------------------------------------------------------
// Kernel P2: g_attn -> A-frags (g_at2)
// ---------------------------------------------------------------------------
__global__ __launch_bounds__(256) void perm_at()
{
    const int total = 64 * 64 * 512;
    int i = blockIdx.x * blockDim.x + threadIdx.x;
    for (; i < total; i += gridDim.x * blockDim.x) {
        const int lane = i & 31, frag = (i >> 5) & 15, kc = (i >> 9) & 63, mblk = i >> 15;
        const int ks = frag & 1, mt = (frag >> 1) & 1, wm = frag >> 2;
        const int g = lane >> 2, t4 = lane & 3;
        const int r0 = mblk * 128 + wm * 32 + mt * 16 + g;
        const int k0 = kc * 16 + ks * 8 + t4;
        const uint32_t* p = g_attn + (size_t)r0 * Dn + k0;
        g_at2[i] = make_uint4(p[0], p[8 * Dn], p[4], p[8 * Dn + 4]);
    }
}

// ---------------------------------------------------------------------------
// Shared GEMM compute step (128x128 warp-tiled, fragment-ordered smem)
// ---------------------------------------------------------------------------
__device__ __forceinline__ void gemm_step(
    const uint4* As, const uint4* Bs, float c[2][8][4],
    int wm, int wn, int lane)
{
    uint4 af[2][2];
    #pragma unroll
    for (int mt = 0; mt < 2; mt++)
        #pragma unroll
        for (int ks = 0; ks < 2; ks++)
            af[mt][ks] = As[(((wm * 2 + mt) * 2) + ks) * 32 + lane];

    #pragma unroll
    for (int nt = 0; nt < 8; nt++) {
        uint4 bf = Bs[(wn * 8 + nt) * 32 + lane];
        mma_tf32(c[0][nt], af[0][0].x, af[0][0].y, af[0][0].z, af[0][0].w, bf.x, bf.y);
        mma_tf32(c[1][nt], af[1][0].x, af[1][0].y, af[1][0].z, af[1][0].w, bf.x, bf.y);
        mma_tf32(c[0][nt], af[0][1].x, af[0][1].y, af[0][1].z, af[0][1].w, bf.z, bf.w);
        mma_tf32(c[1][nt], af[1][1].x, af[1][1].y, af[1][1].z, af[1][1].w, bf.z, bf.w);
    }
}

// One pipeline step with COMPILE-TIME stage indices.
// Entering: chunk CH resident in stage ST, chunk CH+1 copy committed.
// Prefetch CH+2 into stage (ST+2)%3; compute CH; wait so CH+1 is complete.
#define GSTEP(CH, ST) do {                                                    \
    const int _ps = ((ST) + 2) % 3;                                           \
    const bool _pf = (CH) + 2 < 64;                                           \
    if (_pf) {                                                                \
        const uint4* _as = Asrc + (size_t)((CH) + 2) * 512;                   \
        const uint4* _bs = Bsrc + (size_t)((CH) + 2) * 512;                   \
        cp16(&As4[_ps][tid],       _as + tid);                                \
        cp16(&As4[_ps][tid + 256], _as + tid + 256);                          \
        cp16(&Bs4[_ps][tid],       _bs + tid);                                \
        cp16(&Bs4[_ps][tid + 256], _bs + tid + 256);                          \
        CP_COMMIT();                                                          \
    }                                                                         \
    gemm_step(As4[(ST)], Bs4[(ST)], c, wm, wn, lane);                         \
    if (_pf) { CP_WAIT1(); } else if ((CH) + 1 < 64) { CP_WAIT0(); }          \
    __syncthreads();                                                          \
} while (0)

// ---------------------------------------------------------------------------
// Kernel 1: merged QKV projection, 3-stage ring w/ constant stages.
// grid (24, 64), block 256.
// ---------------------------------------------------------------------------
__global__ __launch_bounds__(256) void proj_tc()
{
    const int xx = blockIdx.x;
    const int which = xx >> 3;
    const int nb = xx & 7;
    const int mblk = blockIdx.y;
    const int m0 = mblk * 128;
    const int b = m0 >> 11;
    const int s0 = m0 & 2047;

    uint32_t* outb = (which == 0) ? g_q : (which == 1) ? g_k : g_v;
    const uint4* Asrc = g_xt2 + (size_t)mblk * 64 * 512;
    const uint4* Bsrc = g_wt2 + (size_t)xx * 64 * 512;

    __shared__ uint4 As4[3][512];
    __shared__ uint4 Bs4[3][512];

    const int tid = threadIdx.x, lane = tid & 31, w = tid >> 5;
    const int wm = w >> 1, wn = w & 1;
    const int g = lane >> 2, t4 = lane & 3;

    float c[2][8][4] = {};

    // prime chunks 0,1 into stages 0,1 (one commit group each)
    #pragma unroll
    for (int pc = 0; pc < 2; pc++) {
        const uint4* as = Asrc + (size_t)pc * 512;
        const uint4* bs = Bsrc + (size_t)pc * 512;
        cp16(&As4[pc][tid],       as + tid);
        cp16(&As4[pc][tid + 256], as + tid + 256);
        cp16(&Bs4[pc][tid],       bs + tid);
        cp16(&Bs4[pc][tid + 256], bs + tid + 256);
        CP_COMMIT();
    }
    CP_WAIT1();                 // chunk 0 complete
    __syncthreads();

    for (int t = 0; t < 21; t++) {
        const int ch = 3 * t;
        GSTEP(ch, 0);
        GSTEP(ch + 1, 1);
        GSTEP(ch + 2, 2);
    }
    GSTEP(63, 0);

    const float sc = (which == 0) ? 0.125f : 1.0f;
    const int h0 = nb * 2;
    uint32_t* O = outb + ((size_t)(b * Hn + h0 + wn) * Sn + s0) * HSn;
    #pragma unroll
    for (int mt = 0; mt < 2; mt++) {
        const int r = wm * 32 + mt * 16 + g;
        #pragma unroll
        for (int nt = 0; nt < 8; nt++) {
            const int hs = nt * 8 + 2 * t4;
            *(uint2*)&O[(size_t)r * HSn + hs] =
                make_uint2(f2tf(c[mt][nt][0] * sc), f2tf(c[mt][nt][1] * sc));
            *(uint2*)&O[(size_t)(r + 8) * HSn + hs] =
                make_uint2(f2tf(c[mt][nt][2] * sc), f2tf(c[mt][nt][3] * sc));
        }
    }
}

// ---------------------------------------------------------------------------
// Kernel 2: causal flash attention, fragment-ordered K/V, LPT order.
// grid (16, 64), block 256.  (R12-identical arithmetic.)
// ---------------------------------------------------------------------------
__global__ __launch_bounds__(256) void attn_tc()
{
    const int qt = (int)gridDim.x - 1 - (int)blockIdx.x;   // heavy blocks first
    const int bh = blockIdx.y;
    const int b = bh >> 4, h = bh & 15, q0 = qt * 128;
    const uint32_t* Q = g_q + (size_t)(bh * Sn + q0) * HSn;
    const uint4* Kfg = g_kf + (size_t)bh * 64 * 512;
    const uint4* Vfg = g_vf + (size_t)bh * 64 * 512;

    __shared__ uint4 Kf[2][512];
    __shared__ uint4 Vf[2][512];

    const int tid = threadIdx.x, lane = tid & 31, w = tid >> 5;
    const int g = lane >> 2, t4 = lane & 3, wrow = w * 16;

    uint32_t qf[8][4];
    {
        const uint32_t* Qw = Q + (size_t)(wrow + g) * HSn;
        #pragma unroll
        for (int ks = 0; ks < 8; ks++) {
            const int e = ks * 8 + t4;
            qf[ks][0] = Qw[e];           qf[ks][1] = Qw[8 * HSn + e];
            qf[ks][2] = Qw[e + 4];       qf[ks][3] = Qw[8 * HSn + e + 4];
        }
    }
    float o[8][4] = {};
    float m0 = -1e30f, m1 = -1e30f, l0 = 0.0f, l1 = 0.0f;
    const int rmax = q0 + wrow + 15, jmax = 4 * qt + 3;
    const int srcA = (lane & ~3) | (t4 >> 1), srcB = srcA + 2;
    const bool hi = (t4 & 1) != 0;

    cp16(&Kf[0][tid],       Kfg + tid);
    cp16(&Kf[0][tid + 256], Kfg + tid + 256);
    cp16(&Vf[0][tid],       Vfg + tid);
    cp16(&Vf[0][tid + 256], Vfg + tid + 256);
    CP_COMMIT();

    for (int j = 0; j <= jmax; j++) {
        const int st = j & 1, k0 = j * 32;
        if (j < jmax) {
            const uint4* kp_ = Kfg + (size_t)(j + 1) * 512;
            const uint4* vp_ = Vfg + (size_t)(j + 1) * 512;
            const int ns = st ^ 1;
            cp16(&Kf[ns][tid],       kp_ + tid);
            cp16(&Kf[ns][tid + 256], kp_ + tid + 256);
            cp16(&Vf[ns][tid],       vp_ + tid);
            cp16(&Vf[ns][tid + 256], vp_ + tid + 256);
            CP_COMMIT(); CP_WAIT1();
        } else { CP_WAIT0(); }
        __syncthreads();

        if (k0 <= rmax) {
            float s[4][4] = {};
            #pragma unroll
            for (int nt = 0; nt < 4; nt++) {
                #pragma unroll
                for (int kp = 0; kp < 4; kp++) {
                    uint4 kf = Kf[st][(nt * 4 + kp) * 32 + lane];
                    const int ks0 = 2 * kp;
                    mma_tf32(s[nt], qf[ks0][0], qf[ks0][1], qf[ks0][2], qf[ks0][3], kf.x, kf.y);
                    mma_tf32(s[nt], qf[ks0 + 1][0], qf[ks0 + 1][1], qf[ks0 + 1][2], qf[ks0 + 1][3], kf.z, kf.w);
                }
            }

            const int r0g = q0 + wrow + g, r1g = r0g + 8;
            #pragma unroll
            for (int nt = 0; nt < 4; nt++) {
                const int kc0 = k0 + nt * 8 + 2 * t4;
                if (kc0 > r0g)     s[nt][0] = -1e30f;
                if (kc0 + 1 > r0g) s[nt][1] = -1e30f;
                if (kc0 > r1g)     s[nt][2] = -1e30f;
                if (kc0 + 1 > r1g) s[nt][3] = -1e30f;
            }
            float mx0 = -1e30f, mx1 = -1e30f;
            #pragma unroll
            for (int nt = 0; nt < 4; nt++) {
                mx0 = fmaxf(mx0, fmaxf(s[nt][0], s[nt][1]));
                mx1 = fmaxf(mx1, fmaxf(s[nt][2], s[nt][3]));
            }
            mx0 = fmaxf(mx0, __shfl_xor_sync(~0u, mx0, 1));
            mx0 = fmaxf(mx0, __shfl_xor_sync(~0u, mx0, 2));
            mx1 = fmaxf(mx1, __shfl_xor_sync(~0u, mx1, 1));
            mx1 = fmaxf(mx1, __shfl_xor_sync(~0u, mx1, 2));
            const float mn0 = fmaxf(m0, mx0), mn1 = fmaxf(m1, mx1);
            const float al0 = __expf(m0 - mn0), al1 = __expf(m1 - mn1);
            m0 = mn0; m1 = mn1;

            uint32_t pt[4][4];
            float sum0 = 0.0f, sum1 = 0.0f;
            #pragma unroll
            for (int nt = 0; nt < 4; nt++) {
                float p0 = __expf(s[nt][0] - m0), p1 = __expf(s[nt][1] - m0);
                float p2 = __expf(s[nt][2] - m1), p3 = __expf(s[nt][3] - m1);
                pt[nt][0] = f2tf(p0); pt[nt][1] = f2tf(p1);
                pt[nt][2] = f2tf(p2); pt[nt][3] = f2tf(p3);
                sum0 += __uint_as_float(pt[nt][0]) + __uint_as_float(pt[nt][1]);
                sum1 += __uint_as_float(pt[nt][2]) + __uint_as_float(pt[nt][3]);
            }
            sum0 += __shfl_xor_sync(~0u, sum0, 1); sum0 += __shfl_xor_sync(~0u, sum0, 2);
            sum1 += __shfl_xor_sync(~0u, sum1, 1); sum1 += __shfl_xor_sync(~0u, sum1, 2);
            l0 = l0 * al0 + sum0; l1 = l1 * al1 + sum1;

            #pragma unroll
            for (int nt = 0; nt < 8; nt++) {
                o[nt][0] *= al0; o[nt][1] *= al0;
                o[nt][2] *= al1; o[nt][3] *= al1;
            }

            uint32_t aa[4][4];
            #pragma unroll
            for (int ks = 0; ks < 4; ks++) {
                uint32_t p0a = __shfl_sync(~0u, pt[ks][0], srcA);
                uint32_t p1a = __shfl_sync(~0u, pt[ks][1], srcA);
                uint32_t p2a = __shfl_sync(~0u, pt[ks][2], srcA);
                uint32_t p3a = __shfl_sync(~0u, pt[ks][3], srcA);
                uint32_t p0b = __shfl_sync(~0u, pt[ks][0], srcB);
                uint32_t p1b = __shfl_sync(~0u, pt[ks][1], srcB);
                uint32_t p2b = __shfl_sync(~0u, pt[ks][2], srcB);
                uint32_t p3b = __shfl_sync(~0u, pt[ks][3], srcB);
                aa[ks][0] = hi ? p1a : p0a;
                aa[ks][1] = hi ? p3a : p2a;
                aa[ks][2] = hi ? p1b : p0b;
                aa[ks][3] = hi ? p3b : p2b;
            }

            #pragma unroll
            for (int nt = 0; nt < 8; nt++) {
                #pragma unroll
                for (int kp = 0; kp < 2; kp++) {
                    uint4 vf = Vf[st][(nt * 2 + kp) * 32 + lane];
                    const int ks0 = 2 * kp;
                    mma_tf32(o[nt], aa[ks0][0], aa[ks0][1], aa[ks0][2], aa[ks0][3], vf.x, vf.y);
                    mma_tf32(o[nt], aa[ks0 + 1][0], aa[ks0 + 1][1], aa[ks0 + 1][2], aa[ks0 + 1][3], vf.z, vf.w);
                }
            }
        }
        __syncthreads();
    }
    const float inv0 = 1.0f / l0, inv1 = 1.0f / l1;
    const int row = q0 + wrow + g;
    uint32_t* Ob = g_attn + (size_t)(b * Sn) * Dn + h * HSn;
    #pragma unroll
    for (int nt = 0; nt < 8; nt++) {
        const int hs = nt * 8 + 2 * t4;
        *(uint2*)&Ob[(size_t)row * Dn + hs] =
            make_uint2(f2tf(o[nt][0] * inv0), f2tf(o[nt][1] * inv0));
        *(uint2*)&Ob[(size_t)(row + 8) * Dn + hs] =
            make_uint2(f2tf(o[nt][2] * inv1), f2tf(o[nt][3] * inv1));
    }
}

// ---------------------------------------------------------------------------
// Kernel 3: output projection, 3-stage ring w/ constant stages.
// grid (8, 64), block 256.
// ---------------------------------------------------------------------------
__global__ __launch_bounds__(256) void outproj_tc(
    const float* __restrict__ bo, float* __restrict__ out)
{
    const int nblk = blockIdx.x;
    const int mblk = blockIdx.y;
    const int m0 = mblk * 128;
    const uint4* Asrc = g_at2 + (size_t)mblk * 64 * 512;
    const uint4* Bsrc = g_wo2 + (size_t)nblk * 64 * 512;

    __shared__ uint4 As4[3][512];
    __shared__ uint4 Bs4[3][512];

    const int tid = threadIdx.x, lane = tid & 31, w = tid >> 5;
    const int wm = w >> 1, wn = w & 1;
    const int g = lane >> 2, t4 = lane & 3;

    float c[2][8][4] = {};

    #pragma unroll
    for (int pc = 0; pc < 2; pc++) {
        const uint4* as = Asrc + (size_t)pc * 512;
        const uint4* bs = Bsrc + (size_t)pc * 512;
        cp16(&As4[pc][tid],       as + tid);
        cp16(&As4[pc][tid + 256], as + tid + 256);
        cp16(&Bs4[pc][tid],       bs + tid);
        cp16(&Bs4[pc][tid + 256], bs + tid + 256);
        CP_COMMIT();
    }
    CP_WAIT1();
    __syncthreads();

    for (int t = 0; t < 21; t++) {
        const int ch = 3 * t;
        GSTEP(ch, 0);
        GSTEP(ch + 1, 1);
        GSTEP(ch + 2, 2);
    }
    GSTEP(63, 0);

    float* C = out + (size_t)m0 * Dn + nblk * 128;
    #pragma unroll
    for (int mt = 0; mt < 2; mt++) {
        const int r = wm * 32 + mt * 16 + g;
        #pragma unroll
        for (int nt = 0; nt < 8; nt++) {
            const int n = wn * 64 + nt * 8 + 2 * t4;
            const float2 bias = *(const float2*)&bo[nblk * 128 + n];
            *(float2*)&C[(size_t)r * Dn + n] =
                make_float2(c[mt][nt][0] + bias.x, c[mt][nt][1] + bias.y);
            *(float2*)&C[(size_t)(r + 8) * Dn + n] =
                make_float2(c[mt][nt][2] + bias.x, c[mt][nt][3] + bias.y);
        }
    }
}

// ---------------------------------------------------------------------------
extern "C" void kernel_launch(void* const* d_in, const int* in_sizes, int n_in,
                              void* d_out, int out_size)
{
    const float* X  = (const float*)d_in[0];
    const float* Wq = (const float*)d_in[1];
    const float* Wk = (const float*)d_in[2];
    const float* Wv = (const float*)d_in[3];
    const float* Wo = (const float*)d_in[4];
    const float* bo = (const float*)d_in[5];
    float* out = (float*)d_out;

    cvt_all<<<2048, 256>>>(X, Wq, Wk, Wv, Wo);
    proj_tc<<<dim3(24, 64), 256>>>();
    perm_kv<<<2048, 256>>>();
    attn_tc<<<dim3(16, 64), 256>>>();
    perm_at<<<2048, 256>>>();
    outproj_tc<<<dim3(8, 64), 256>>>(bo, out);
}

// round 15
// speedup vs baseline: 1.1261x; 1.1261x over previous
#include <cuda_runtime.h>
#include <cstdint>

constexpr int Bn = 4, Sn = 2048, Dn = 1024, Hn = 16, HSn = 64;

// Scratch (tf32 bit patterns)
__device__ uint32_t g_q[Bn * Hn * Sn * HSn];
__device__ uint32_t g_k[Bn * Hn * Sn * HSn];
__device__ uint32_t g_v[Bn * Hn * Sn * HSn];
// Fragment-ordered operand buffers (layouts documented in R12):
__device__ uint4 g_xt2[64 * 64 * 512];
__device__ uint4 g_wt2[24 * 64 * 512];
__device__ uint4 g_at2[64 * 64 * 512];   // written directly by attn epilogue
__device__ uint4 g_wo2[8 * 64 * 512];
__device__ uint4 g_kf[64 * 64 * 512];
__device__ uint4 g_vf[64 * 64 * 512];

__device__ __forceinline__ uint32_t f2tf(float x) {
    uint32_t r; asm("cvt.rna.tf32.f32 %0, %1;" : "=r"(r) : "f"(x)); return r;
}
__device__ __forceinline__ void mma_tf32(float c[4], uint32_t a0, uint32_t a1,
                                         uint32_t a2, uint32_t a3, uint32_t b0, uint32_t b1) {
    asm volatile("mma.sync.aligned.m16n8k8.row.col.f32.tf32.tf32.f32 "
        "{%0,%1,%2,%3}, {%4,%5,%6,%7}, {%8,%9}, {%0,%1,%2,%3};\n"
        : "+f"(c[0]), "+f"(c[1]), "+f"(c[2]), "+f"(c[3])
        : "r"(a0), "r"(a1), "r"(a2), "r"(a3), "r"(b0), "r"(b1));
}
__device__ __forceinline__ void cp16(void* s, const void* g) {
    uint32_t d = (uint32_t)__cvta_generic_to_shared(s);
    asm volatile("cp.async.ca.shared.global [%0], [%1], 16;\n" :: "r"(d), "l"(g));
}
#define CP_COMMIT() asm volatile("cp.async.commit_group;\n" ::: "memory")
#define CP_WAIT0()  asm volatile("cp.async.wait_group 0;\n" ::: "memory")
#define CP_WAIT1()  asm volatile("cp.async.wait_group 1;\n" ::: "memory")

// ---------------------------------------------------------------------------
// Kernel 0: fused prep — X->A-frags, Wq/Wk/Wv->B-frags, Wo->B-frags
// ---------------------------------------------------------------------------
constexpr int NXF = 64 * 64 * 512;
constexpr int NWF = 24 * 64 * 512;
constexpr int NOF = 8 * 64 * 512;

__global__ __launch_bounds__(256) void cvt_all(
    const float* __restrict__ X,  const float* __restrict__ Wq,
    const float* __restrict__ Wk, const float* __restrict__ Wv,
    const float* __restrict__ Wo)
{
    const int total = NXF + NWF + NOF;
    int i = blockIdx.x * blockDim.x + threadIdx.x;
    for (; i < total; i += gridDim.x * blockDim.x) {
        if (i < NXF) {
            const int lane = i & 31, frag = (i >> 5) & 15, kc = (i >> 9) & 63, mblk = i >> 15;
            const int ks = frag & 1, mt = (frag >> 1) & 1, wm = frag >> 2;
            const int g = lane >> 2, t4 = lane & 3;
            const int r0 = mblk * 128 + wm * 32 + mt * 16 + g;
            const int k0 = kc * 16 + ks * 8 + t4;
            const float* p = X + (size_t)r0 * Dn + k0;
            g_xt2[i] = make_uint4(f2tf(p[0]), f2tf(p[8 * Dn]), f2tf(p[4]), f2tf(p[8 * Dn + 4]));
        } else if (i < NXF + NWF) {
            const int j = i - NXF;
            const int lane = j & 31, frag = (j >> 5) & 15, kc = (j >> 9) & 63, blk = j >> 15;
            const int which = blk >> 3, nb = blk & 7;
            const int nt = frag & 7, wn = frag >> 3;
            const int g = lane >> 2, t4 = lane & 3;
            const int n_local = wn * 64 + nt * 8 + g;
            const int head = nb * 2 + (n_local >= 64 ? 1 : 0);
            const int e = n_local & 63;
            const float* W = (which == 0) ? Wq : (which == 1) ? Wk : Wv;
            const float* p = W + ((size_t)head * Dn + kc * 16) * HSn + e;
            g_wt2[j] = make_uint4(f2tf(p[(size_t)t4 * HSn]), f2tf(p[(size_t)(t4 + 4) * HSn]),
                                  f2tf(p[(size_t)(8 + t4) * HSn]), f2tf(p[(size_t)(12 + t4) * HSn]));
        } else {
            const int j = i - NXF - NWF;
            const int lane = j & 31, frag = (j >> 5) & 15, kc = (j >> 9) & 63, nblk = j >> 15;
            const int nt = frag & 7, wn = frag >> 3;
            const int g = lane >> 2, t4 = lane & 3;
            const int n = nblk * 128 + wn * 64 + nt * 8 + g;
            const int k0 = kc * 16 + t4;
            const float* p = Wo + (size_t)k0 * Dn + n;
            g_wo2[j] = make_uint4(f2tf(p[0]), f2tf(p[4 * Dn]), f2tf(p[8 * Dn]), f2tf(p[12 * Dn]));
        }
    }
}

// ---------------------------------------------------------------------------
// Kernel P1: K,V -> attn B-frags (g_kf, g_vf)
// ---------------------------------------------------------------------------
__global__ __launch_bounds__(256) void perm_kv()
{
    const int total = 64 * 64 * 512;
    int i = blockIdx.x * blockDim.x + threadIdx.x;
    for (; i < 2 * total; i += gridDim.x * blockDim.x) {
        const bool isV = i >= total;
        const int j = isV ? i - total : i;
        const int lane = j & 31, frag = (j >> 5) & 15, jt = (j >> 9) & 63, bh = j >> 15;
        const int g = lane >> 2, t4 = lane & 3;
        if (!isV) {
            const int nt = frag >> 2, kp = frag & 3;
            const int n = jt * 32 + nt * 8 + g;
            const uint32_t* p = g_k + ((size_t)bh * Sn + n) * HSn + kp * 16 + t4;
            g_kf[j] = make_uint4(p[0], p[4], p[8], p[12]);
        } else {
            const int nt = frag >> 1, kp = frag & 1;
            const int hs = nt * 8 + g;
            const int k0 = jt * 32 + kp * 16 + t4;
            const uint32_t* p = g_v + ((size_t)bh * Sn + k0) * HSn + hs;
            g_vf[j] = make_uint4(p[0], p[4 * HSn], p[8 * HSn], p[12 * HSn]);
        }
    }
}

// ---------------------------------------------------------------------------
// Shared GEMM compute step (128x128 warp-tiled, fragment-ordered smem)
// ---------------------------------------------------------------------------
__device__ __forceinline__ void gemm_step(
    const uint4* As, const uint4* Bs, float c[2][8][4],
    int wm, int wn, int lane)
{
    uint4 af[2][2];
    #pragma unroll
    for (int mt = 0; mt < 2; mt++)
        #pragma unroll
        for (int ks = 0; ks < 2; ks++)
            af[mt][ks] = As[(((wm * 2 + mt) * 2) + ks) * 32 + lane];

    #pragma unroll
    for (int nt = 0; nt < 8; nt++) {
        uint4 bf = Bs[(wn * 8 + nt) * 32 + lane];
        mma_tf32(c[0][nt], af[0][0].x, af[0][0].y, af[0][0].z, af[0][0].w, bf.x, bf.y);
        mma_tf32(c[1][nt], af[1][0].x, af[1][0].y, af[1][0].z, af[1][0].w, bf.x, bf.y);
        mma_tf32(c[0][nt], af[0][1].x, af[0][1].y, af[0][1].z, af[0][1].w, bf.z, bf.w);
        mma_tf32(c[1][nt], af[1][1].x, af[1][1].y, af[1][1].z, af[1][1].w, bf.z, bf.w);
    }
}

// ---------------------------------------------------------------------------
// Kernel 1: merged QKV projection (R12-exact 2-stage). grid (24, 64).
// ---------------------------------------------------------------------------
__global__ __launch_bounds__(256) void proj_tc()
{
    const int xx = blockIdx.x;
    const int which = xx >> 3;
    const int nb = xx & 7;
    const int mblk = blockIdx.y;
    const int m0 = mblk * 128;
    const int b = m0 >> 11;
    const int s0 = m0 & 2047;

    uint32_t* outb = (which == 0) ? g_q : (which == 1) ? g_k : g_v;
    const uint4* Asrc = g_xt2 + (size_t)mblk * 64 * 512;
    const uint4* Bsrc = g_wt2 + (size_t)xx * 64 * 512;

    __shared__ uint4 As4[2][512];
    __shared__ uint4 Bs4[2][512];

    const int tid = threadIdx.x, lane = tid & 31, w = tid >> 5;
    const int wm = w >> 1, wn = w & 1;
    const int g = lane >> 2, t4 = lane & 3;

    float c[2][8][4] = {};

    cp16(&As4[0][tid],       Asrc + tid);
    cp16(&As4[0][tid + 256], Asrc + tid + 256);
    cp16(&Bs4[0][tid],       Bsrc + tid);
    cp16(&Bs4[0][tid + 256], Bsrc + tid + 256);
    CP_COMMIT();
    CP_WAIT0();
    __syncthreads();

    int buf = 0;
    for (int ch = 0; ch < 64; ch++) {
        const bool more = (ch + 1 < 64);
        if (more) {
            const uint4* as = Asrc + (size_t)(ch + 1) * 512;
            const uint4* bs = Bsrc + (size_t)(ch + 1) * 512;
            const int nbuf = buf ^ 1;
            cp16(&As4[nbuf][tid],       as + tid);
            cp16(&As4[nbuf][tid + 256], as + tid + 256);
            cp16(&Bs4[nbuf][tid],       bs + tid);
            cp16(&Bs4[nbuf][tid + 256], bs + tid + 256);
            CP_COMMIT();
        }

        gemm_step(As4[buf], Bs4[buf], c, wm, wn, lane);

        if (more) CP_WAIT0();
        __syncthreads();
        buf ^= 1;
    }

    const float sc = (which == 0) ? 0.125f : 1.0f;
    const int h0 = nb * 2;
    uint32_t* O = outb + ((size_t)(b * Hn + h0 + wn) * Sn + s0) * HSn;
    #pragma unroll
    for (int mt = 0; mt < 2; mt++) {
        const int r = wm * 32 + mt * 16 + g;
        #pragma unroll
        for (int nt = 0; nt < 8; nt++) {
            const int hs = nt * 8 + 2 * t4;
            *(uint2*)&O[(size_t)r * HSn + hs] =
                make_uint2(f2tf(c[mt][nt][0] * sc), f2tf(c[mt][nt][1] * sc));
            *(uint2*)&O[(size_t)(r + 8) * HSn + hs] =
                make_uint2(f2tf(c[mt][nt][2] * sc), f2tf(c[mt][nt][3] * sc));
        }
    }
}

// ---------------------------------------------------------------------------
// Kernel 2: causal flash attention, fragment-ordered K/V (R12-exact mainloop).
// Epilogue writes outproj A-frags directly to g_at2 (perm_at fused).
// grid (16, 64), block 256.
// ---------------------------------------------------------------------------
__global__ __launch_bounds__(256) void attn_tc()
{
    const int qt = blockIdx.x, bh = blockIdx.y;
    const int b = bh >> 4, h = bh & 15, q0 = qt * 128;
    const uint32_t* Q = g_q + (size_t)(bh * Sn + q0) * HSn;
    const uint4* Kfg = g_kf + (size_t)bh * 64 * 512;
    const uint4* Vfg = g_vf + (size_t)bh * 64 * 512;

    __shared__ uint4 Kf[2][512];
    __shared__ uint4 Vf[2][512];

    const int tid = threadIdx.x, lane = tid & 31, w = tid >> 5;
    const int g = lane >> 2, t4 = lane & 3, wrow = w * 16;

    uint32_t qf[8][4];
    {
        const uint32_t* Qw = Q + (size_t)(wrow + g) * HSn;
        #pragma unroll
        for (int ks = 0; ks < 8; ks++) {
            const int e = ks * 8 + t4;
            qf[ks][0] = Qw[e];           qf[ks][1] = Qw[8 * HSn + e];
            qf[ks][2] = Qw[e + 4];       qf[ks][3] = Qw[8 * HSn + e + 4];
        }
    }
    float o[8][4] = {};
    float m0 = -1e30f, m1 = -1e30f, l0 = 0.0f, l1 = 0.0f;
    const int rmax = q0 + wrow + 15, jmax = 4 * qt + 3;
    const int srcA = (lane & ~3) | (t4 >> 1), srcB = srcA + 2;
    const bool hi = (t4 & 1) != 0;

    cp16(&Kf[0][tid],       Kfg + tid);
    cp16(&Kf[0][tid + 256], Kfg + tid + 256);
    cp16(&Vf[0][tid],       Vfg + tid);
    cp16(&Vf[0][tid + 256], Vfg + tid + 256);
    CP_COMMIT();

    for (int j = 0; j <= jmax; j++) {
        const int st = j & 1, k0 = j * 32;
        if (j < jmax) {
            const uint4* kp_ = Kfg + (size_t)(j + 1) * 512;
            const uint4* vp_ = Vfg + (size_t)(j + 1) * 512;
            const int ns = st ^ 1;
            cp16(&Kf[ns][tid],       kp_ + tid);
            cp16(&Kf[ns][tid + 256], kp_ + tid + 256);
            cp16(&Vf[ns][tid],       vp_ + tid);
            cp16(&Vf[ns][tid + 256], vp_ + tid + 256);
            CP_COMMIT(); CP_WAIT1();
        } else { CP_WAIT0(); }
        __syncthreads();

        if (k0 <= rmax) {
            float s[4][4] = {};
            #pragma unroll
            for (int nt = 0; nt < 4; nt++) {
                #pragma unroll
                for (int kp = 0; kp < 4; kp++) {
                    uint4 kf = Kf[st][(nt * 4 + kp) * 32 + lane];
                    const int ks0 = 2 * kp;
                    mma_tf32(s[nt], qf[ks0][0], qf[ks0][1], qf[ks0][2], qf[ks0][3], kf.x, kf.y);
                    mma_tf32(s[nt], qf[ks0 + 1][0], qf[ks0 + 1][1], qf[ks0 + 1][2], qf[ks0 + 1][3], kf.z, kf.w);
                }
            }

            const int r0g = q0 + wrow + g, r1g = r0g + 8;
            #pragma unroll
            for (int nt = 0; nt < 4; nt++) {
                const int kc0 = k0 + nt * 8 + 2 * t4;
                if (kc0 > r0g)     s[nt][0] = -1e30f;
                if (kc0 + 1 > r0g) s[nt][1] = -1e30f;
                if (kc0 > r1g)     s[nt][2] = -1e30f;
                if (kc0 + 1 > r1g) s[nt][3] = -1e30f;
            }
            float mx0 = -1e30f, mx1 = -1e30f;
            #pragma unroll
            for (int nt = 0; nt < 4; nt++) {
                mx0 = fmaxf(mx0, fmaxf(s[nt][0], s[nt][1]));
                mx1 = fmaxf(mx1, fmaxf(s[nt][2], s[nt][3]));
            }
            mx0 = fmaxf(mx0, __shfl_xor_sync(~0u, mx0, 1));
            mx0 = fmaxf(mx0, __shfl_xor_sync(~0u, mx0, 2));
            mx1 = fmaxf(mx1, __shfl_xor_sync(~0u, mx1, 1));
            mx1 = fmaxf(mx1, __shfl_xor_sync(~0u, mx1, 2));
            const float mn0 = fmaxf(m0, mx0), mn1 = fmaxf(m1, mx1);
            const float al0 = __expf(m0 - mn0), al1 = __expf(m1 - mn1);
            m0 = mn0; m1 = mn1;

            uint32_t pt[4][4];
            float sum0 = 0.0f, sum1 = 0.0f;
            #pragma unroll
            for (int nt = 0; nt < 4; nt++) {
                float p0 = __expf(s[nt][0] - m0), p1 = __expf(s[nt][1] - m0);
                float p2 = __expf(s[nt][2] - m1), p3 = __expf(s[nt][3] - m1);
                pt[nt][0] = f2tf(p0); pt[nt][1] = f2tf(p1);
                pt[nt][2] = f2tf(p2); pt[nt][3] = f2tf(p3);
                sum0 += __uint_as_float(pt[nt][0]) + __uint_as_float(pt[nt][1]);
                sum1 += __uint_as_float(pt[nt][2]) + __uint_as_float(pt[nt][3]);
            }
            sum0 += __shfl_xor_sync(~0u, sum0, 1); sum0 += __shfl_xor_sync(~0u, sum0, 2);
            sum1 += __shfl_xor_sync(~0u, sum1, 1); sum1 += __shfl_xor_sync(~0u, sum1, 2);
            l0 = l0 * al0 + sum0; l1 = l1 * al1 + sum1;

            #pragma unroll
            for (int nt = 0; nt < 8; nt++) {
                o[nt][0] *= al0; o[nt][1] *= al0;
                o[nt][2] *= al1; o[nt][3] *= al1;
            }

            uint32_t aa[4][4];
            #pragma unroll
            for (int ks = 0; ks < 4; ks++) {
                uint32_t p0a = __shfl_sync(~0u, pt[ks][0], srcA);
                uint32_t p1a = __shfl_sync(~0u, pt[ks][1], srcA);
                uint32_t p2a = __shfl_sync(~0u, pt[ks][2], srcA);
                uint32_t p3a = __shfl_sync(~0u, pt[ks][3], srcA);
                uint32_t p0b = __shfl_sync(~0u, pt[ks][0], srcB);
                uint32_t p1b = __shfl_sync(~0u, pt[ks][1], srcB);
                uint32_t p2b = __shfl_sync(~0u, pt[ks][2], srcB);
                uint32_t p3b = __shfl_sync(~0u, pt[ks][3], srcB);
                aa[ks][0] = hi ? p1a : p0a;
                aa[ks][1] = hi ? p3a : p2a;
                aa[ks][2] = hi ? p1b : p0b;
                aa[ks][3] = hi ? p3b : p2b;
            }

            #pragma unroll
            for (int nt = 0; nt < 8; nt++) {
                #pragma unroll
                for (int kp = 0; kp < 2; kp++) {
                    uint4 vf = Vf[st][(nt * 2 + kp) * 32 + lane];
                    const int ks0 = 2 * kp;
                    mma_tf32(o[nt], aa[ks0][0], aa[ks0][1], aa[ks0][2], aa[ks0][3], vf.x, vf.y);
                    mma_tf32(o[nt], aa[ks0 + 1][0], aa[ks0 + 1][1], aa[ks0 + 1][2], aa[ks0 + 1][3], vf.z, vf.w);
                }
            }
        }
        __syncthreads();
    }

    // Epilogue: normalize, tf32-round, relayout C-frag -> A-frag via the same
    // quad shuffles, and write outproj A-frags directly to g_at2.
    // Dest row block: mblk = b*16 + qt; frag = 2*w + ks; kc = h*4 + lc, nt = lc*2+ks.
    const float inv0 = 1.0f / l0, inv1 = 1.0f / l1;
    const int mblk = b * 16 + qt;
    #pragma unroll
    for (int nt = 0; nt < 8; nt++) {
        const uint32_t u0 = f2tf(o[nt][0] * inv0);
        const uint32_t u1 = f2tf(o[nt][1] * inv0);
        const uint32_t u2 = f2tf(o[nt][2] * inv1);
        const uint32_t u3 = f2tf(o[nt][3] * inv1);
        const uint32_t p0a = __shfl_sync(~0u, u0, srcA);
        const uint32_t p1a = __shfl_sync(~0u, u1, srcA);
        const uint32_t p2a = __shfl_sync(~0u, u2, srcA);
        const uint32_t p3a = __shfl_sync(~0u, u3, srcA);
        const uint32_t p0b = __shfl_sync(~0u, u0, srcB);
        const uint32_t p1b = __shfl_sync(~0u, u1, srcB);
        const uint32_t p2b = __shfl_sync(~0u, u2, srcB);
        const uint32_t p3b = __shfl_sync(~0u, u3, srcB);
        uint4 v;
        v.x = hi ? p1a : p0a;   // O[g][nt*8+t4]
        v.y = hi ? p3a : p2a;   // O[g+8][nt*8+t4]
        v.z = hi ? p1b : p0b;   // O[g][nt*8+t4+4]
        v.w = hi ? p3b : p2b;   // O[g+8][nt*8+t4+4]
        const int lc = nt >> 1, ks = nt & 1;
        const int kc = h * 4 + lc;
        const int frag = 2 * w + ks;
        g_at2[(((size_t)mblk * 64 + kc) * 16 + frag) * 32 + lane] = v;
    }
}

// ---------------------------------------------------------------------------
// Kernel 3: output projection (R12-exact 2-stage). grid (8, 64), block 256.
// ---------------------------------------------------------------------------
__global__ __launch_bounds__(256) void outproj_tc(
    const float* __restrict__ bo, float* __restrict__ out)
{
    const int nblk = blockIdx.x;
    const int mblk = blockIdx.y;
    const int m0 = mblk * 128;
    const uint4* Asrc = g_at2 + (size_t)mblk * 64 * 512;
    const uint4* Bsrc = g_wo2 + (size_t)nblk * 64 * 512;

    __shared__ uint4 As4[2][512];
    __shared__ uint4 Bs4[2][512];

    const int tid = threadIdx.x, lane = tid & 31, w = tid >> 5;
    const int wm = w >> 1, wn = w & 1;
    const int g = lane >> 2, t4 = lane & 3;

    float c[2][8][4] = {};

    cp16(&As4[0][tid],       Asrc + tid);
    cp16(&As4[0][tid + 256], Asrc + tid + 256);
    cp16(&Bs4[0][tid],       Bsrc + tid);
    cp16(&Bs4[0][tid + 256], Bsrc + tid + 256);
    CP_COMMIT();
    CP_WAIT0();
    __syncthreads();

    int buf = 0;
    for (int ch = 0; ch < 64; ch++) {
        const bool more = (ch + 1 < 64);
        if (more) {
            const uint4* as = Asrc + (size_t)(ch + 1) * 512;
            const uint4* bs = Bsrc + (size_t)(ch + 1) * 512;
            const int nbuf = buf ^ 1;
            cp16(&As4[nbuf][tid],       as + tid);
            cp16(&As4[nbuf][tid + 256], as + tid + 256);
            cp16(&Bs4[nbuf][tid],       bs + tid);
            cp16(&Bs4[nbuf][tid + 256], bs + tid + 256);
            CP_COMMIT();
        }

        gemm_step(As4[buf], Bs4[buf], c, wm, wn, lane);

        if (more) CP_WAIT0();
        __syncthreads();
        buf ^= 1;
    }

    float* C = out + (size_t)m0 * Dn + nblk * 128;
    #pragma unroll
    for (int mt = 0; mt < 2; mt++) {
        const int r = wm * 32 + mt * 16 + g;
        #pragma unroll
        for (int nt = 0; nt < 8; nt++) {
            const int n = wn * 64 + nt * 8 + 2 * t4;
            const float2 bias = *(const float2*)&bo[nblk * 128 + n];
            *(float2*)&C[(size_t)r * Dn + n] =
                make_float2(c[mt][nt][0] + bias.x, c[mt][nt][1] + bias.y);
            *(float2*)&C[(size_t)(r + 8) * Dn + n] =
                make_float2(c[mt][nt][2] + bias.x, c[mt][nt][3] + bias.y);
        }
    }
}

// ---------------------------------------------------------------------------
extern "C" void kernel_launch(void* const* d_in, const int* in_sizes, int n_in,
                              void* d_out, int out_size)
{
    const float* X  = (const float*)d_in[0];
    const float* Wq = (const float*)d_in[1];
    const float* Wk = (const float*)d_in[2];
    const float* Wv = (const float*)d_in[3];
    const float* Wo = (const float*)d_in[4];
    const float* bo = (const float*)d_in[5];
    float* out = (float*)d_out;

    cvt_all<<<2048, 256>>>(X, Wq, Wk, Wv, Wo);
    proj_tc<<<dim3(24, 64), 256>>>();
    perm_kv<<<2048, 256>>>();
    attn_tc<<<dim3(16, 64), 256>>>();
    outproj_tc<<<dim3(8, 64), 256>>>(bo, out);
}

// round 16
// speedup vs baseline: 1.1414x; 1.0136x over previous
#include <cuda_runtime.h>
#include <cstdint>

constexpr int Bn = 4, Sn = 2048, Dn = 1024, Hn = 16, HSn = 64;

// Scratch (tf32 bit patterns)
__device__ uint32_t g_q[Bn * Hn * Sn * HSn];
__device__ uint32_t g_k[Bn * Hn * Sn * HSn];
__device__ uint32_t g_v[Bn * Hn * Sn * HSn];
// Fragment-ordered operand buffers (layouts documented in R12):
__device__ uint4 g_xt2[64 * 64 * 512];
__device__ uint4 g_wt2[24 * 64 * 512];
__device__ uint4 g_at2[64 * 64 * 512];   // written directly by attn epilogue
__device__ uint4 g_wo2[8 * 64 * 512];
__device__ uint4 g_kf[64 * 64 * 512];
__device__ uint4 g_vf[64 * 64 * 512];

__device__ __forceinline__ uint32_t f2tf(float x) {
    uint32_t r; asm("cvt.rna.tf32.f32 %0, %1;" : "=r"(r) : "f"(x)); return r;
}
__device__ __forceinline__ float ex2(float x) {
    float r; asm("ex2.approx.f32 %0, %1;" : "=f"(r) : "f"(x)); return r;
}
__device__ __forceinline__ void mma_tf32(float c[4], uint32_t a0, uint32_t a1,
                                         uint32_t a2, uint32_t a3, uint32_t b0, uint32_t b1) {
    asm volatile("mma.sync.aligned.m16n8k8.row.col.f32.tf32.tf32.f32 "
        "{%0,%1,%2,%3}, {%4,%5,%6,%7}, {%8,%9}, {%0,%1,%2,%3};\n"
        : "+f"(c[0]), "+f"(c[1]), "+f"(c[2]), "+f"(c[3])
        : "r"(a0), "r"(a1), "r"(a2), "r"(a3), "r"(b0), "r"(b1));
}
__device__ __forceinline__ void cp16(void* s, const void* g) {
    uint32_t d = (uint32_t)__cvta_generic_to_shared(s);
    asm volatile("cp.async.ca.shared.global [%0], [%1], 16;\n" :: "r"(d), "l"(g));
}
#define CP_COMMIT() asm volatile("cp.async.commit_group;\n" ::: "memory")
#define CP_WAIT0()  asm volatile("cp.async.wait_group 0;\n" ::: "memory")
#define CP_WAIT1()  asm volatile("cp.async.wait_group 1;\n" ::: "memory")

// ---------------------------------------------------------------------------
// Kernel 0: fused prep — X->A-frags, Wq/Wk/Wv->B-frags, Wo->B-frags
// ---------------------------------------------------------------------------
constexpr int NXF = 64 * 64 * 512;
constexpr int NWF = 24 * 64 * 512;
constexpr int NOF = 8 * 64 * 512;

__global__ __launch_bounds__(256) void cvt_all(
    const float* __restrict__ X,  const float* __restrict__ Wq,
    const float* __restrict__ Wk, const float* __restrict__ Wv,
    const float* __restrict__ Wo)
{
    const int total = NXF + NWF + NOF;
    int i = blockIdx.x * blockDim.x + threadIdx.x;
    for (; i < total; i += gridDim.x * blockDim.x) {
        if (i < NXF) {
            const int lane = i & 31, frag = (i >> 5) & 15, kc = (i >> 9) & 63, mblk = i >> 15;
            const int ks = frag & 1, mt = (frag >> 1) & 1, wm = frag >> 2;
            const int g = lane >> 2, t4 = lane & 3;
            const int r0 = mblk * 128 + wm * 32 + mt * 16 + g;
            const int k0 = kc * 16 + ks * 8 + t4;
            const float* p = X + (size_t)r0 * Dn + k0;
            g_xt2[i] = make_uint4(f2tf(p[0]), f2tf(p[8 * Dn]), f2tf(p[4]), f2tf(p[8 * Dn + 4]));
        } else if (i < NXF + NWF) {
            const int j = i - NXF;
            const int lane = j & 31, frag = (j >> 5) & 15, kc = (j >> 9) & 63, blk = j >> 15;
            const int which = blk >> 3, nb = blk & 7;
            const int nt = frag & 7, wn = frag >> 3;
            const int g = lane >> 2, t4 = lane & 3;
            const int n_local = wn * 64 + nt * 8 + g;
            const int head = nb * 2 + (n_local >= 64 ? 1 : 0);
            const int e = n_local & 63;
            const float* W = (which == 0) ? Wq : (which == 1) ? Wk : Wv;
            const float* p = W + ((size_t)head * Dn + kc * 16) * HSn + e;
            g_wt2[j] = make_uint4(f2tf(p[(size_t)t4 * HSn]), f2tf(p[(size_t)(t4 + 4) * HSn]),
                                  f2tf(p[(size_t)(8 + t4) * HSn]), f2tf(p[(size_t)(12 + t4) * HSn]));
        } else {
            const int j = i - NXF - NWF;
            const int lane = j & 31, frag = (j >> 5) & 15, kc = (j >> 9) & 63, nblk = j >> 15;
            const int nt = frag & 7, wn = frag >> 3;
            const int g = lane >> 2, t4 = lane & 3;
            const int n = nblk * 128 + wn * 64 + nt * 8 + g;
            const int k0 = kc * 16 + t4;
            const float* p = Wo + (size_t)k0 * Dn + n;
            g_wo2[j] = make_uint4(f2tf(p[0]), f2tf(p[4 * Dn]), f2tf(p[8 * Dn]), f2tf(p[12 * Dn]));
        }
    }
}

// ---------------------------------------------------------------------------
// Kernel P1: K,V -> attn B-frags (g_kf, g_vf)
// ---------------------------------------------------------------------------
__global__ __launch_bounds__(256) void perm_kv()
{
    const int total = 64 * 64 * 512;
    int i = blockIdx.x * blockDim.x + threadIdx.x;
    for (; i < 2 * total; i += gridDim.x * blockDim.x) {
        const bool isV = i >= total;
        const int j = isV ? i - total : i;
        const int lane = j & 31, frag = (j >> 5) & 15, jt = (j >> 9) & 63, bh = j >> 15;
        const int g = lane >> 2, t4 = lane & 3;
        if (!isV) {
            const int nt = frag >> 2, kp = frag & 3;
            const int n = jt * 32 + nt * 8 + g;
            const uint32_t* p = g_k + ((size_t)bh * Sn + n) * HSn + kp * 16 + t4;
            g_kf[j] = make_uint4(p[0], p[4], p[8], p[12]);
        } else {
            const int nt = frag >> 1, kp = frag & 1;
            const int hs = nt * 8 + g;
            const int k0 = jt * 32 + kp * 16 + t4;
            const uint32_t* p = g_v + ((size_t)bh * Sn + k0) * HSn + hs;
            g_vf[j] = make_uint4(p[0], p[4 * HSn], p[8 * HSn], p[12 * HSn]);
        }
    }
}

// ---------------------------------------------------------------------------
// Shared GEMM compute step (128x128 warp-tiled, fragment-ordered smem)
// ---------------------------------------------------------------------------
__device__ __forceinline__ void gemm_step(
    const uint4* As, const uint4* Bs, float c[2][8][4],
    int wm, int wn, int lane)
{
    uint4 af[2][2];
    #pragma unroll
    for (int mt = 0; mt < 2; mt++)
        #pragma unroll
        for (int ks = 0; ks < 2; ks++)
            af[mt][ks] = As[(((wm * 2 + mt) * 2) + ks) * 32 + lane];

    #pragma unroll
    for (int nt = 0; nt < 8; nt++) {
        uint4 bf = Bs[(wn * 8 + nt) * 32 + lane];
        mma_tf32(c[0][nt], af[0][0].x, af[0][0].y, af[0][0].z, af[0][0].w, bf.x, bf.y);
        mma_tf32(c[1][nt], af[1][0].x, af[1][0].y, af[1][0].z, af[1][0].w, bf.x, bf.y);
        mma_tf32(c[0][nt], af[0][1].x, af[0][1].y, af[0][1].z, af[0][1].w, bf.z, bf.w);
        mma_tf32(c[1][nt], af[1][1].x, af[1][1].y, af[1][1].z, af[1][1].w, bf.z, bf.w);
    }
}

// ---------------------------------------------------------------------------
// Kernel 1: merged QKV projection (R12-exact 2-stage). grid (24, 64).
// Q is pre-scaled by 0.125 * log2(e) for the exp2-domain softmax.
// ---------------------------------------------------------------------------
__global__ __launch_bounds__(256) void proj_tc()
{
    const int xx = blockIdx.x;
    const int which = xx >> 3;
    const int nb = xx & 7;
    const int mblk = blockIdx.y;
    const int m0 = mblk * 128;
    const int b = m0 >> 11;
    const int s0 = m0 & 2047;

    uint32_t* outb = (which == 0) ? g_q : (which == 1) ? g_k : g_v;
    const uint4* Asrc = g_xt2 + (size_t)mblk * 64 * 512;
    const uint4* Bsrc = g_wt2 + (size_t)xx * 64 * 512;

    __shared__ uint4 As4[2][512];
    __shared__ uint4 Bs4[2][512];

    const int tid = threadIdx.x, lane = tid & 31, w = tid >> 5;
    const int wm = w >> 1, wn = w & 1;
    const int g = lane >> 2, t4 = lane & 3;

    float c[2][8][4] = {};

    cp16(&As4[0][tid],       Asrc + tid);
    cp16(&As4[0][tid + 256], Asrc + tid + 256);
    cp16(&Bs4[0][tid],       Bsrc + tid);
    cp16(&Bs4[0][tid + 256], Bsrc + tid + 256);
    CP_COMMIT();
    CP_WAIT0();
    __syncthreads();

    int buf = 0;
    for (int ch = 0; ch < 64; ch++) {
        const bool more = (ch + 1 < 64);
        if (more) {
            const uint4* as = Asrc + (size_t)(ch + 1) * 512;
            const uint4* bs = Bsrc + (size_t)(ch + 1) * 512;
            const int nbuf = buf ^ 1;
            cp16(&As4[nbuf][tid],       as + tid);
            cp16(&As4[nbuf][tid + 256], as + tid + 256);
            cp16(&Bs4[nbuf][tid],       bs + tid);
            cp16(&Bs4[nbuf][tid + 256], bs + tid + 256);
            CP_COMMIT();
        }

        gemm_step(As4[buf], Bs4[buf], c, wm, wn, lane);

        if (more) CP_WAIT0();
        __syncthreads();
        buf ^= 1;
    }

    // Q scale folds in log2(e) so attention softmax can use raw ex2.
    const float sc = (which == 0) ? 0.125f * 1.44269504088896340736f : 1.0f;
    const int h0 = nb * 2;
    uint32_t* O = outb + ((size_t)(b * Hn + h0 + wn) * Sn + s0) * HSn;
    #pragma unroll
    for (int mt = 0; mt < 2; mt++) {
        const int r = wm * 32 + mt * 16 + g;
        #pragma unroll
        for (int nt = 0; nt < 8; nt++) {
            const int hs = nt * 8 + 2 * t4;
            *(uint2*)&O[(size_t)r * HSn + hs] =
                make_uint2(f2tf(c[mt][nt][0] * sc), f2tf(c[mt][nt][1] * sc));
            *(uint2*)&O[(size_t)(r + 8) * HSn + hs] =
                make_uint2(f2tf(c[mt][nt][2] * sc), f2tf(c[mt][nt][3] * sc));
        }
    }
}

// ---------------------------------------------------------------------------
// Kernel 2: causal flash attention, exp2-domain softmax, warp-uniform mask
// skip, fused A-frag epilogue. grid (16, 64), block 256.
// ---------------------------------------------------------------------------
__global__ __launch_bounds__(256) void attn_tc()
{
    const int qt = blockIdx.x, bh = blockIdx.y;
    const int b = bh >> 4, h = bh & 15, q0 = qt * 128;
    const uint32_t* Q = g_q + (size_t)(bh * Sn + q0) * HSn;
    const uint4* Kfg = g_kf + (size_t)bh * 64 * 512;
    const uint4* Vfg = g_vf + (size_t)bh * 64 * 512;

    __shared__ uint4 Kf[2][512];
    __shared__ uint4 Vf[2][512];

    const int tid = threadIdx.x, lane = tid & 31, w = tid >> 5;
    const int g = lane >> 2, t4 = lane & 3, wrow = w * 16;

    uint32_t qf[8][4];
    {
        const uint32_t* Qw = Q + (size_t)(wrow + g) * HSn;
        #pragma unroll
        for (int ks = 0; ks < 8; ks++) {
            const int e = ks * 8 + t4;
            qf[ks][0] = Qw[e];           qf[ks][1] = Qw[8 * HSn + e];
            qf[ks][2] = Qw[e + 4];       qf[ks][3] = Qw[8 * HSn + e + 4];
        }
    }
    float o[8][4] = {};
    float m0 = -1e30f, m1 = -1e30f, l0 = 0.0f, l1 = 0.0f;
    const int rmax = q0 + wrow + 15, jmax = 4 * qt + 3;
    const int srcA = (lane & ~3) | (t4 >> 1), srcB = srcA + 2;
    const bool hi = (t4 & 1) != 0;

    cp16(&Kf[0][tid],       Kfg + tid);
    cp16(&Kf[0][tid + 256], Kfg + tid + 256);
    cp16(&Vf[0][tid],       Vfg + tid);
    cp16(&Vf[0][tid + 256], Vfg + tid + 256);
    CP_COMMIT();

    for (int j = 0; j <= jmax; j++) {
        const int st = j & 1, k0 = j * 32;
        if (j < jmax) {
            const uint4* kp_ = Kfg + (size_t)(j + 1) * 512;
            const uint4* vp_ = Vfg + (size_t)(j + 1) * 512;
            const int ns = st ^ 1;
            cp16(&Kf[ns][tid],       kp_ + tid);
            cp16(&Kf[ns][tid + 256], kp_ + tid + 256);
            cp16(&Vf[ns][tid],       vp_ + tid);
            cp16(&Vf[ns][tid + 256], vp_ + tid + 256);
            CP_COMMIT(); CP_WAIT1();
        } else { CP_WAIT0(); }
        __syncthreads();

        if (k0 <= rmax) {
            float s[4][4] = {};
            #pragma unroll
            for (int nt = 0; nt < 4; nt++) {
                #pragma unroll
                for (int kp = 0; kp < 4; kp++) {
                    uint4 kf = Kf[st][(nt * 4 + kp) * 32 + lane];
                    const int ks0 = 2 * kp;
                    mma_tf32(s[nt], qf[ks0][0], qf[ks0][1], qf[ks0][2], qf[ks0][3], kf.x, kf.y);
                    mma_tf32(s[nt], qf[ks0 + 1][0], qf[ks0 + 1][1], qf[ks0 + 1][2], qf[ks0 + 1][3], kf.z, kf.w);
                }
            }

            // causal mask — only diagonal-straddling tiles need it (warp-uniform)
            if (k0 + 31 > q0 + wrow) {
                const int r0g = q0 + wrow + g, r1g = r0g + 8;
                #pragma unroll
                for (int nt = 0; nt < 4; nt++) {
                    const int kc0 = k0 + nt * 8 + 2 * t4;
                    if (kc0 > r0g)     s[nt][0] = -1e30f;
                    if (kc0 + 1 > r0g) s[nt][1] = -1e30f;
                    if (kc0 > r1g)     s[nt][2] = -1e30f;
                    if (kc0 + 1 > r1g) s[nt][3] = -1e30f;
                }
            }

            float mx0 = -1e30f, mx1 = -1e30f;
            #pragma unroll
            for (int nt = 0; nt < 4; nt++) {
                mx0 = fmaxf(mx0, fmaxf(s[nt][0], s[nt][1]));
                mx1 = fmaxf(mx1, fmaxf(s[nt][2], s[nt][3]));
            }
            mx0 = fmaxf(mx0, __shfl_xor_sync(~0u, mx0, 1));
            mx0 = fmaxf(mx0, __shfl_xor_sync(~0u, mx0, 2));
            mx1 = fmaxf(mx1, __shfl_xor_sync(~0u, mx1, 1));
            mx1 = fmaxf(mx1, __shfl_xor_sync(~0u, mx1, 2));
            const float mn0 = fmaxf(m0, mx0), mn1 = fmaxf(m1, mx1);
            const float al0 = ex2(m0 - mn0), al1 = ex2(m1 - mn1);
            m0 = mn0; m1 = mn1;

            uint32_t pt[4][4];
            float sum0 = 0.0f, sum1 = 0.0f;
            #pragma unroll
            for (int nt = 0; nt < 4; nt++) {
                float p0 = ex2(s[nt][0] - m0), p1 = ex2(s[nt][1] - m0);
                float p2 = ex2(s[nt][2] - m1), p3 = ex2(s[nt][3] - m1);
                pt[nt][0] = f2tf(p0); pt[nt][1] = f2tf(p1);
                pt[nt][2] = f2tf(p2); pt[nt][3] = f2tf(p3);
                sum0 += __uint_as_float(pt[nt][0]) + __uint_as_float(pt[nt][1]);
                sum1 += __uint_as_float(pt[nt][2]) + __uint_as_float(pt[nt][3]);
            }
            sum0 += __shfl_xor_sync(~0u, sum0, 1); sum0 += __shfl_xor_sync(~0u, sum0, 2);
            sum1 += __shfl_xor_sync(~0u, sum1, 1); sum1 += __shfl_xor_sync(~0u, sum1, 2);
            l0 = l0 * al0 + sum0; l1 = l1 * al1 + sum1;

            #pragma unroll
            for (int nt = 0; nt < 8; nt++) {
                o[nt][0] *= al0; o[nt][1] *= al0;
                o[nt][2] *= al1; o[nt][3] *= al1;
            }

            uint32_t aa[4][4];
            #pragma unroll
            for (int ks = 0; ks < 4; ks++) {
                uint32_t p0a = __shfl_sync(~0u, pt[ks][0], srcA);
                uint32_t p1a = __shfl_sync(~0u, pt[ks][1], srcA);
                uint32_t p2a = __shfl_sync(~0u, pt[ks][2], srcA);
                uint32_t p3a = __shfl_sync(~0u, pt[ks][3], srcA);
                uint32_t p0b = __shfl_sync(~0u, pt[ks][0], srcB);
                uint32_t p1b = __shfl_sync(~0u, pt[ks][1], srcB);
                uint32_t p2b = __shfl_sync(~0u, pt[ks][2], srcB);
                uint32_t p3b = __shfl_sync(~0u, pt[ks][3], srcB);
                aa[ks][0] = hi ? p1a : p0a;
                aa[ks][1] = hi ? p3a : p2a;
                aa[ks][2] = hi ? p1b : p0b;
                aa[ks][3] = hi ? p3b : p2b;
            }

            #pragma unroll
            for (int nt = 0; nt < 8; nt++) {
                #pragma unroll
                for (int kp = 0; kp < 2; kp++) {
                    uint4 vf = Vf[st][(nt * 2 + kp) * 32 + lane];
                    const int ks0 = 2 * kp;
                    mma_tf32(o[nt], aa[ks0][0], aa[ks0][1], aa[ks0][2], aa[ks0][3], vf.x, vf.y);
                    mma_tf32(o[nt], aa[ks0 + 1][0], aa[ks0 + 1][1], aa[ks0 + 1][2], aa[ks0 + 1][3], vf.z, vf.w);
                }
            }
        }
        __syncthreads();
    }

    // Epilogue: normalize, tf32-round, relayout C->A frags, write to g_at2.
    const float inv0 = 1.0f / l0, inv1 = 1.0f / l1;
    const int mblk = b * 16 + qt;
    #pragma unroll
    for (int nt = 0; nt < 8; nt++) {
        const uint32_t u0 = f2tf(o[nt][0] * inv0);
        const uint32_t u1 = f2tf(o[nt][1] * inv0);
        const uint32_t u2 = f2tf(o[nt][2] * inv1);
        const uint32_t u3 = f2tf(o[nt][3] * inv1);
        const uint32_t p0a = __shfl_sync(~0u, u0, srcA);
        const uint32_t p1a = __shfl_sync(~0u, u1, srcA);
        const uint32_t p2a = __shfl_sync(~0u, u2, srcA);
        const uint32_t p3a = __shfl_sync(~0u, u3, srcA);
        const uint32_t p0b = __shfl_sync(~0u, u0, srcB);
        const uint32_t p1b = __shfl_sync(~0u, u1, srcB);
        const uint32_t p2b = __shfl_sync(~0u, u2, srcB);
        const uint32_t p3b = __shfl_sync(~0u, u3, srcB);
        uint4 v;
        v.x = hi ? p1a : p0a;
        v.y = hi ? p3a : p2a;
        v.z = hi ? p1b : p0b;
        v.w = hi ? p3b : p2b;
        const int lc = nt >> 1, ks = nt & 1;
        const int kc = h * 4 + lc;
        const int frag = 2 * w + ks;
        g_at2[(((size_t)mblk * 64 + kc) * 16 + frag) * 32 + lane] = v;
    }
}

// ---------------------------------------------------------------------------
// Kernel 3: output projection (R12-exact 2-stage). grid (8, 64), block 256.
// ---------------------------------------------------------------------------
__global__ __launch_bounds__(256) void outproj_tc(
    const float* __restrict__ bo, float* __restrict__ out)
{
    const int nblk = blockIdx.x;
    const int mblk = blockIdx.y;
    const int m0 = mblk * 128;
    const uint4* Asrc = g_at2 + (size_t)mblk * 64 * 512;
    const uint4* Bsrc = g_wo2 + (size_t)nblk * 64 * 512;

    __shared__ uint4 As4[2][512];
    __shared__ uint4 Bs4[2][512];

    const int tid = threadIdx.x, lane = tid & 31, w = tid >> 5;
    const int wm = w >> 1, wn = w & 1;
    const int g = lane >> 2, t4 = lane & 3;

    float c[2][8][4] = {};

    cp16(&As4[0][tid],       Asrc + tid);
    cp16(&As4[0][tid + 256], Asrc + tid + 256);
    cp16(&Bs4[0][tid],       Bsrc + tid);
    cp16(&Bs4[0][tid + 256], Bsrc + tid + 256);
    CP_COMMIT();
    CP_WAIT0();
    __syncthreads();

    int buf = 0;
    for (int ch = 0; ch < 64; ch++) {
        const bool more = (ch + 1 < 64);
        if (more) {
            const uint4* as = Asrc + (size_t)(ch + 1) * 512;
            const uint4* bs = Bsrc + (size_t)(ch + 1) * 512;
            const int nbuf = buf ^ 1;
            cp16(&As4[nbuf][tid],       as + tid);
            cp16(&As4[nbuf][tid + 256], as + tid + 256);
            cp16(&Bs4[nbuf][tid],       bs + tid);
            cp16(&Bs4[nbuf][tid + 256], bs + tid + 256);
            CP_COMMIT();
        }

        gemm_step(As4[buf], Bs4[buf], c, wm, wn, lane);

        if (more) CP_WAIT0();
        __syncthreads();
        buf ^= 1;
    }

    float* C = out + (size_t)m0 * Dn + nblk * 128;
    #pragma unroll
    for (int mt = 0; mt < 2; mt++) {
        const int r = wm * 32 + mt * 16 + g;
        #pragma unroll
        for (int nt = 0; nt < 8; nt++) {
            const int n = wn * 64 + nt * 8 + 2 * t4;
            const float2 bias = *(const float2*)&bo[nblk * 128 + n];
            *(float2*)&C[(size_t)r * Dn + n] =
                make_float2(c[mt][nt][0] + bias.x, c[mt][nt][1] + bias.y);
            *(float2*)&C[(size_t)(r + 8) * Dn + n] =
                make_float2(c[mt][nt][2] + bias.x, c[mt][nt][3] + bias.y);
        }
    }
}

// ---------------------------------------------------------------------------
extern "C" void kernel_launch(void* const* d_in, const int* in_sizes, int n_in,
                              void* d_out, int out_size)
{
    const float* X  = (const float*)d_in[0];
    const float* Wq = (const float*)d_in[1];
    const float* Wk = (const float*)d_in[2];
    const float* Wv = (const float*)d_in[3];
    const float* Wo = (const float*)d_in[4];
    const float* bo = (const float*)d_in[5];
    float* out = (float*)d_out;

    cvt_all<<<2048, 256>>>(X, Wq, Wk, Wv, Wo);
    proj_tc<<<dim3(24, 64), 256>>>();
    perm_kv<<<2048, 256>>>();
    attn_tc<<<dim3(16, 64), 256>>>();
    outproj_tc<<<dim3(8, 64), 256>>>(bo, out);
}

// round 17
// speedup vs baseline: 1.1525x; 1.0097x over previous
#include <cuda_runtime.h>
#include <cstdint>

constexpr int Bn = 4, Sn = 2048, Dn = 1024, Hn = 16, HSn = 64;

// Scratch (tf32 bit patterns)
__device__ uint32_t g_q[Bn * Hn * Sn * HSn];
__device__ uint32_t g_k[Bn * Hn * Sn * HSn];
__device__ uint32_t g_v[Bn * Hn * Sn * HSn];
// Fragment-ordered operand buffers (layouts documented in R12):
__device__ uint4 g_xt2[64 * 64 * 512];
__device__ uint4 g_wt2[24 * 64 * 512];
__device__ uint4 g_at2[64 * 64 * 512];   // written directly by attn epilogue
__device__ uint4 g_wo2[8 * 64 * 512];
__device__ uint4 g_kf[64 * 64 * 512];
__device__ uint4 g_vf[64 * 64 * 512];

__device__ __forceinline__ uint32_t f2tf(float x) {
    uint32_t r; asm("cvt.rna.tf32.f32 %0, %1;" : "=r"(r) : "f"(x)); return r;
}
__device__ __forceinline__ float ex2(float x) {
    float r; asm("ex2.approx.f32 %0, %1;" : "=f"(r) : "f"(x)); return r;
}
__device__ __forceinline__ void mma_tf32(float c[4], uint32_t a0, uint32_t a1,
                                         uint32_t a2, uint32_t a3, uint32_t b0, uint32_t b1) {
    asm volatile("mma.sync.aligned.m16n8k8.row.col.f32.tf32.tf32.f32 "
        "{%0,%1,%2,%3}, {%4,%5,%6,%7}, {%8,%9}, {%0,%1,%2,%3};\n"
        : "+f"(c[0]), "+f"(c[1]), "+f"(c[2]), "+f"(c[3])
        : "r"(a0), "r"(a1), "r"(a2), "r"(a3), "r"(b0), "r"(b1));
}
__device__ __forceinline__ void cp16(void* s, const void* g) {
    uint32_t d = (uint32_t)__cvta_generic_to_shared(s);
    asm volatile("cp.async.ca.shared.global [%0], [%1], 16;\n" :: "r"(d), "l"(g));
}
#define CP_COMMIT() asm volatile("cp.async.commit_group;\n" ::: "memory")
#define CP_WAIT0()  asm volatile("cp.async.wait_group 0;\n" ::: "memory")
#define CP_WAIT1()  asm volatile("cp.async.wait_group 1;\n" ::: "memory")

// ---------------------------------------------------------------------------
// Kernel 0: fused prep — X->A-frags, Wq/Wk/Wv->B-frags, Wo->B-frags
// ---------------------------------------------------------------------------
constexpr int NXF = 64 * 64 * 512;
constexpr int NWF = 24 * 64 * 512;
constexpr int NOF = 8 * 64 * 512;

__global__ __launch_bounds__(256) void cvt_all(
    const float* __restrict__ X,  const float* __restrict__ Wq,
    const float* __restrict__ Wk, const float* __restrict__ Wv,
    const float* __restrict__ Wo)
{
    const int total = NXF + NWF + NOF;
    int i = blockIdx.x * blockDim.x + threadIdx.x;
    for (; i < total; i += gridDim.x * blockDim.x) {
        if (i < NXF) {
            const int lane = i & 31, frag = (i >> 5) & 15, kc = (i >> 9) & 63, mblk = i >> 15;
            const int ks = frag & 1, mt = (frag >> 1) & 1, wm = frag >> 2;
            const int g = lane >> 2, t4 = lane & 3;
            const int r0 = mblk * 128 + wm * 32 + mt * 16 + g;
            const int k0 = kc * 16 + ks * 8 + t4;
            const float* p = X + (size_t)r0 * Dn + k0;
            g_xt2[i] = make_uint4(f2tf(p[0]), f2tf(p[8 * Dn]), f2tf(p[4]), f2tf(p[8 * Dn + 4]));
        } else if (i < NXF + NWF) {
            const int j = i - NXF;
            const int lane = j & 31, frag = (j >> 5) & 15, kc = (j >> 9) & 63, blk = j >> 15;
            const int which = blk >> 3, nb = blk & 7;
            const int nt = frag & 7, wn = frag >> 3;
            const int g = lane >> 2, t4 = lane & 3;
            const int n_local = wn * 64 + nt * 8 + g;
            const int head = nb * 2 + (n_local >= 64 ? 1 : 0);
            const int e = n_local & 63;
            const float* W = (which == 0) ? Wq : (which == 1) ? Wk : Wv;
            const float* p = W + ((size_t)head * Dn + kc * 16) * HSn + e;
            g_wt2[j] = make_uint4(f2tf(p[(size_t)t4 * HSn]), f2tf(p[(size_t)(t4 + 4) * HSn]),
                                  f2tf(p[(size_t)(8 + t4) * HSn]), f2tf(p[(size_t)(12 + t4) * HSn]));
        } else {
            const int j = i - NXF - NWF;
            const int lane = j & 31, frag = (j >> 5) & 15, kc = (j >> 9) & 63, nblk = j >> 15;
            const int nt = frag & 7, wn = frag >> 3;
            const int g = lane >> 2, t4 = lane & 3;
            const int n = nblk * 128 + wn * 64 + nt * 8 + g;
            const int k0 = kc * 16 + t4;
            const float* p = Wo + (size_t)k0 * Dn + n;
            g_wo2[j] = make_uint4(f2tf(p[0]), f2tf(p[4 * Dn]), f2tf(p[8 * Dn]), f2tf(p[12 * Dn]));
        }
    }
}

// ---------------------------------------------------------------------------
// Kernel P1: K,V -> attn B-frags (g_kf, g_vf)
// ---------------------------------------------------------------------------
__global__ __launch_bounds__(256) void perm_kv()
{
    const int total = 64 * 64 * 512;
    int i = blockIdx.x * blockDim.x + threadIdx.x;
    for (; i < 2 * total; i += gridDim.x * blockDim.x) {
        const bool isV = i >= total;
        const int j = isV ? i - total : i;
        const int lane = j & 31, frag = (j >> 5) & 15, jt = (j >> 9) & 63, bh = j >> 15;
        const int g = lane >> 2, t4 = lane & 3;
        if (!isV) {
            const int nt = frag >> 2, kp = frag & 3;
            const int n = jt * 32 + nt * 8 + g;
            const uint32_t* p = g_k + ((size_t)bh * Sn + n) * HSn + kp * 16 + t4;
            g_kf[j] = make_uint4(p[0], p[4], p[8], p[12]);
        } else {
            const int nt = frag >> 1, kp = frag & 1;
            const int hs = nt * 8 + g;
            const int k0 = jt * 32 + kp * 16 + t4;
            const uint32_t* p = g_v + ((size_t)bh * Sn + k0) * HSn + hs;
            g_vf[j] = make_uint4(p[0], p[4 * HSn], p[8 * HSn], p[12 * HSn]);
        }
    }
}

// ---------------------------------------------------------------------------
// Shared GEMM compute step (128x128 warp-tiled, fragment-ordered smem)
// ---------------------------------------------------------------------------
__device__ __forceinline__ void gemm_step(
    const uint4* As, const uint4* Bs, float c[2][8][4],
    int wm, int wn, int lane)
{
    uint4 af[2][2];
    #pragma unroll
    for (int mt = 0; mt < 2; mt++)
        #pragma unroll
        for (int ks = 0; ks < 2; ks++)
            af[mt][ks] = As[(((wm * 2 + mt) * 2) + ks) * 32 + lane];

    #pragma unroll
    for (int nt = 0; nt < 8; nt++) {
        uint4 bf = Bs[(wn * 8 + nt) * 32 + lane];
        mma_tf32(c[0][nt], af[0][0].x, af[0][0].y, af[0][0].z, af[0][0].w, bf.x, bf.y);
        mma_tf32(c[1][nt], af[1][0].x, af[1][0].y, af[1][0].z, af[1][0].w, bf.x, bf.y);
        mma_tf32(c[0][nt], af[0][1].x, af[0][1].y, af[0][1].z, af[0][1].w, bf.z, bf.w);
        mma_tf32(c[1][nt], af[1][1].x, af[1][1].y, af[1][1].z, af[1][1].w, bf.z, bf.w);
    }
}

// ---------------------------------------------------------------------------
// Kernel 1: merged QKV projection (R12-exact 2-stage). grid (24, 64).
// Q is pre-scaled by 0.125 * log2(e) for the exp2-domain softmax.
// ---------------------------------------------------------------------------
__global__ __launch_bounds__(256) void proj_tc()
{
    const int xx = blockIdx.x;
    const int which = xx >> 3;
    const int nb = xx & 7;
    const int mblk = blockIdx.y;
    const int m0 = mblk * 128;
    const int b = m0 >> 11;
    const int s0 = m0 & 2047;

    uint32_t* outb = (which == 0) ? g_q : (which == 1) ? g_k : g_v;
    const uint4* Asrc = g_xt2 + (size_t)mblk * 64 * 512;
    const uint4* Bsrc = g_wt2 + (size_t)xx * 64 * 512;

    __shared__ uint4 As4[2][512];
    __shared__ uint4 Bs4[2][512];

    const int tid = threadIdx.x, lane = tid & 31, w = tid >> 5;
    const int wm = w >> 1, wn = w & 1;
    const int g = lane >> 2, t4 = lane & 3;

    float c[2][8][4] = {};

    cp16(&As4[0][tid],       Asrc + tid);
    cp16(&As4[0][tid + 256], Asrc + tid + 256);
    cp16(&Bs4[0][tid],       Bsrc + tid);
    cp16(&Bs4[0][tid + 256], Bsrc + tid + 256);
    CP_COMMIT();
    CP_WAIT0();
    __syncthreads();

    int buf = 0;
    for (int ch = 0; ch < 64; ch++) {
        const bool more = (ch + 1 < 64);
        if (more) {
            const uint4* as = Asrc + (size_t)(ch + 1) * 512;
            const uint4* bs = Bsrc + (size_t)(ch + 1) * 512;
            const int nbuf = buf ^ 1;
            cp16(&As4[nbuf][tid],       as + tid);
            cp16(&As4[nbuf][tid + 256], as + tid + 256);
            cp16(&Bs4[nbuf][tid],       bs + tid);
            cp16(&Bs4[nbuf][tid + 256], bs + tid + 256);
            CP_COMMIT();
        }

        gemm_step(As4[buf], Bs4[buf], c, wm, wn, lane);

        if (more) CP_WAIT0();
        __syncthreads();
        buf ^= 1;
    }

    // Q scale folds in log2(e) so attention softmax can use raw ex2.
    const float sc = (which == 0) ? 0.125f * 1.44269504088896340736f : 1.0f;
    const int h0 = nb * 2;
    uint32_t* O = outb + ((size_t)(b * Hn + h0 + wn) * Sn + s0) * HSn;
    #pragma unroll
    for (int mt = 0; mt < 2; mt++) {
        const int r = wm * 32 + mt * 16 + g;
        #pragma unroll
        for (int nt = 0; nt < 8; nt++) {
            const int hs = nt * 8 + 2 * t4;
            *(uint2*)&O[(size_t)r * HSn + hs] =
                make_uint2(f2tf(c[mt][nt][0] * sc), f2tf(c[mt][nt][1] * sc));
            *(uint2*)&O[(size_t)(r + 8) * HSn + hs] =
                make_uint2(f2tf(c[mt][nt][2] * sc), f2tf(c[mt][nt][3] * sc));
        }
    }
}

// ---------------------------------------------------------------------------
// Kernel 2: causal flash attention, exp2 softmax, SINGLE barrier per tile.
// Order: wait(fill of current stage) -> barrier (publishes fill AND closes
// previous iteration's reads) -> prefetch next stage -> compute.
// grid (16, 64), block 256.
// ---------------------------------------------------------------------------
__global__ __launch_bounds__(256) void attn_tc()
{
    const int qt = blockIdx.x, bh = blockIdx.y;
    const int b = bh >> 4, h = bh & 15, q0 = qt * 128;
    const uint32_t* Q = g_q + (size_t)(bh * Sn + q0) * HSn;
    const uint4* Kfg = g_kf + (size_t)bh * 64 * 512;
    const uint4* Vfg = g_vf + (size_t)bh * 64 * 512;

    __shared__ uint4 Kf[2][512];
    __shared__ uint4 Vf[2][512];

    const int tid = threadIdx.x, lane = tid & 31, w = tid >> 5;
    const int g = lane >> 2, t4 = lane & 3, wrow = w * 16;

    uint32_t qf[8][4];
    {
        const uint32_t* Qw = Q + (size_t)(wrow + g) * HSn;
        #pragma unroll
        for (int ks = 0; ks < 8; ks++) {
            const int e = ks * 8 + t4;
            qf[ks][0] = Qw[e];           qf[ks][1] = Qw[8 * HSn + e];
            qf[ks][2] = Qw[e + 4];       qf[ks][3] = Qw[8 * HSn + e + 4];
        }
    }
    float o[8][4] = {};
    float m0 = -1e30f, m1 = -1e30f, l0 = 0.0f, l1 = 0.0f;
    const int rmax = q0 + wrow + 15, jmax = 4 * qt + 3;
    const int srcA = (lane & ~3) | (t4 >> 1), srcB = srcA + 2;
    const bool hi = (t4 & 1) != 0;
    const int r0g = q0 + wrow + g, r1g = r0g + 8;

    // prime stage 0 with tile 0
    cp16(&Kf[0][tid],       Kfg + tid);
    cp16(&Kf[0][tid + 256], Kfg + tid + 256);
    cp16(&Vf[0][tid],       Vfg + tid);
    cp16(&Vf[0][tid + 256], Vfg + tid + 256);
    CP_COMMIT();

    for (int j = 0; j <= jmax; j++) {
        const int st = j & 1, k0 = j * 32;

        CP_WAIT0();          // current stage's fill (issued last iter) complete
        __syncthreads();     // publish fill; all warps done reading st^1

        if (j < jmax) {      // prefetch next tile into st^1 (safe post-barrier)
            const uint4* kp_ = Kfg + (size_t)(j + 1) * 512;
            const uint4* vp_ = Vfg + (size_t)(j + 1) * 512;
            const int ns = st ^ 1;
            cp16(&Kf[ns][tid],       kp_ + tid);
            cp16(&Kf[ns][tid + 256], kp_ + tid + 256);
            cp16(&Vf[ns][tid],       vp_ + tid);
            cp16(&Vf[ns][tid + 256], vp_ + tid + 256);
            CP_COMMIT();
        }

        if (k0 <= rmax) {
            float s[4][4] = {};
            #pragma unroll
            for (int nt = 0; nt < 4; nt++) {
                #pragma unroll
                for (int kp = 0; kp < 4; kp++) {
                    uint4 kf = Kf[st][(nt * 4 + kp) * 32 + lane];
                    const int ks0 = 2 * kp;
                    mma_tf32(s[nt], qf[ks0][0], qf[ks0][1], qf[ks0][2], qf[ks0][3], kf.x, kf.y);
                    mma_tf32(s[nt], qf[ks0 + 1][0], qf[ks0 + 1][1], qf[ks0 + 1][2], qf[ks0 + 1][3], kf.z, kf.w);
                }
            }

            if (k0 + 31 > q0 + wrow) {   // diagonal tiles only (warp-uniform)
                #pragma unroll
                for (int nt = 0; nt < 4; nt++) {
                    const int kc0 = k0 + nt * 8 + 2 * t4;
                    if (kc0 > r0g)     s[nt][0] = -1e30f;
                    if (kc0 + 1 > r0g) s[nt][1] = -1e30f;
                    if (kc0 > r1g)     s[nt][2] = -1e30f;
                    if (kc0 + 1 > r1g) s[nt][3] = -1e30f;
                }
            }

            float mx0 = -1e30f, mx1 = -1e30f;
            #pragma unroll
            for (int nt = 0; nt < 4; nt++) {
                mx0 = fmaxf(mx0, fmaxf(s[nt][0], s[nt][1]));
                mx1 = fmaxf(mx1, fmaxf(s[nt][2], s[nt][3]));
            }
            mx0 = fmaxf(mx0, __shfl_xor_sync(~0u, mx0, 1));
            mx0 = fmaxf(mx0, __shfl_xor_sync(~0u, mx0, 2));
            mx1 = fmaxf(mx1, __shfl_xor_sync(~0u, mx1, 1));
            mx1 = fmaxf(mx1, __shfl_xor_sync(~0u, mx1, 2));
            const float mn0 = fmaxf(m0, mx0), mn1 = fmaxf(m1, mx1);
            const float al0 = ex2(m0 - mn0), al1 = ex2(m1 - mn1);
            m0 = mn0; m1 = mn1;

            uint32_t pt[4][4];
            float sum0 = 0.0f, sum1 = 0.0f;
            #pragma unroll
            for (int nt = 0; nt < 4; nt++) {
                float p0 = ex2(s[nt][0] - m0), p1 = ex2(s[nt][1] - m0);
                float p2 = ex2(s[nt][2] - m1), p3 = ex2(s[nt][3] - m1);
                pt[nt][0] = f2tf(p0); pt[nt][1] = f2tf(p1);
                pt[nt][2] = f2tf(p2); pt[nt][3] = f2tf(p3);
                sum0 += __uint_as_float(pt[nt][0]) + __uint_as_float(pt[nt][1]);
                sum1 += __uint_as_float(pt[nt][2]) + __uint_as_float(pt[nt][3]);
            }
            sum0 += __shfl_xor_sync(~0u, sum0, 1); sum0 += __shfl_xor_sync(~0u, sum0, 2);
            sum1 += __shfl_xor_sync(~0u, sum1, 1); sum1 += __shfl_xor_sync(~0u, sum1, 2);
            l0 = l0 * al0 + sum0; l1 = l1 * al1 + sum1;

            #pragma unroll
            for (int nt = 0; nt < 8; nt++) {
                o[nt][0] *= al0; o[nt][1] *= al0;
                o[nt][2] *= al1; o[nt][3] *= al1;
            }

            uint32_t aa[4][4];
            #pragma unroll
            for (int ks = 0; ks < 4; ks++) {
                uint32_t p0a = __shfl_sync(~0u, pt[ks][0], srcA);
                uint32_t p1a = __shfl_sync(~0u, pt[ks][1], srcA);
                uint32_t p2a = __shfl_sync(~0u, pt[ks][2], srcA);
                uint32_t p3a = __shfl_sync(~0u, pt[ks][3], srcA);
                uint32_t p0b = __shfl_sync(~0u, pt[ks][0], srcB);
                uint32_t p1b = __shfl_sync(~0u, pt[ks][1], srcB);
                uint32_t p2b = __shfl_sync(~0u, pt[ks][2], srcB);
                uint32_t p3b = __shfl_sync(~0u, pt[ks][3], srcB);
                aa[ks][0] = hi ? p1a : p0a;
                aa[ks][1] = hi ? p3a : p2a;
                aa[ks][2] = hi ? p1b : p0b;
                aa[ks][3] = hi ? p3b : p2b;
            }

            #pragma unroll
            for (int nt = 0; nt < 8; nt++) {
                #pragma unroll
                for (int kp = 0; kp < 2; kp++) {
                    uint4 vf = Vf[st][(nt * 2 + kp) * 32 + lane];
                    const int ks0 = 2 * kp;
                    mma_tf32(o[nt], aa[ks0][0], aa[ks0][1], aa[ks0][2], aa[ks0][3], vf.x, vf.y);
                    mma_tf32(o[nt], aa[ks0 + 1][0], aa[ks0 + 1][1], aa[ks0 + 1][2], aa[ks0 + 1][3], vf.z, vf.w);
                }
            }
        }
    }

    // Epilogue: normalize, tf32-round, relayout C->A frags, write to g_at2.
    const float inv0 = 1.0f / l0, inv1 = 1.0f / l1;
    const int mblk = b * 16 + qt;
    #pragma unroll
    for (int nt = 0; nt < 8; nt++) {
        const uint32_t u0 = f2tf(o[nt][0] * inv0);
        const uint32_t u1 = f2tf(o[nt][1] * inv0);
        const uint32_t u2 = f2tf(o[nt][2] * inv1);
        const uint32_t u3 = f2tf(o[nt][3] * inv1);
        const uint32_t p0a = __shfl_sync(~0u, u0, srcA);
        const uint32_t p1a = __shfl_sync(~0u, u1, srcA);
        const uint32_t p2a = __shfl_sync(~0u, u2, srcA);
        const uint32_t p3a = __shfl_sync(~0u, u3, srcA);
        const uint32_t p0b = __shfl_sync(~0u, u0, srcB);
        const uint32_t p1b = __shfl_sync(~0u, u1, srcB);
        const uint32_t p2b = __shfl_sync(~0u, u2, srcB);
        const uint32_t p3b = __shfl_sync(~0u, u3, srcB);
        uint4 v;
        v.x = hi ? p1a : p0a;
        v.y = hi ? p3a : p2a;
        v.z = hi ? p1b : p0b;
        v.w = hi ? p3b : p2b;
        const int lc = nt >> 1, ks = nt & 1;
        const int kc = h * 4 + lc;
        const int frag = 2 * w + ks;
        g_at2[(((size_t)mblk * 64 + kc) * 16 + frag) * 32 + lane] = v;
    }
}

// ---------------------------------------------------------------------------
// Kernel 3: output projection (R12-exact 2-stage). grid (8, 64), block 256.
// ---------------------------------------------------------------------------
__global__ __launch_bounds__(256) void outproj_tc(
    const float* __restrict__ bo, float* __restrict__ out)
{
    const int nblk = blockIdx.x;
    const int mblk = blockIdx.y;
    const int m0 = mblk * 128;
    const uint4* Asrc = g_at2 + (size_t)mblk * 64 * 512;
    const uint4* Bsrc = g_wo2 + (size_t)nblk * 64 * 512;

    __shared__ uint4 As4[2][512];
    __shared__ uint4 Bs4[2][512];

    const int tid = threadIdx.x, lane = tid & 31, w = tid >> 5;
    const int wm = w >> 1, wn = w & 1;
    const int g = lane >> 2, t4 = lane & 3;

    float c[2][8][4] = {};

    cp16(&As4[0][tid],       Asrc + tid);
    cp16(&As4[0][tid + 256], Asrc + tid + 256);
    cp16(&Bs4[0][tid],       Bsrc + tid);
    cp16(&Bs4[0][tid + 256], Bsrc + tid + 256);
    CP_COMMIT();
    CP_WAIT0();
    __syncthreads();

    int buf = 0;
    for (int ch = 0; ch < 64; ch++) {
        const bool more = (ch + 1 < 64);
        if (more) {
            const uint4* as = Asrc + (size_t)(ch + 1) * 512;
            const uint4* bs = Bsrc + (size_t)(ch + 1) * 512;
            const int nbuf = buf ^ 1;
            cp16(&As4[nbuf][tid],       as + tid);
            cp16(&As4[nbuf][tid + 256], as + tid + 256);
            cp16(&Bs4[nbuf][tid],       bs + tid);
            cp16(&Bs4[nbuf][tid + 256], bs + tid + 256);
            CP_COMMIT();
        }

        gemm_step(As4[buf], Bs4[buf], c, wm, wn, lane);

        if (more) CP_WAIT0();
        __syncthreads();
        buf ^= 1;
    }

    float* C = out + (size_t)m0 * Dn + nblk * 128;
    #pragma unroll
    for (int mt = 0; mt < 2; mt++) {
        const int r = wm * 32 + mt * 16 + g;
        #pragma unroll
        for (int nt = 0; nt < 8; nt++) {
            const int n = wn * 64 + nt * 8 + 2 * t4;
            const float2 bias = *(const float2*)&bo[nblk * 128 + n];
            *(float2*)&C[(size_t)r * Dn + n] =
                make_float2(c[mt][nt][0] + bias.x, c[mt][nt][1] + bias.y);
            *(float2*)&C[(size_t)(r + 8) * Dn + n] =
                make_float2(c[mt][nt][2] + bias.x, c[mt][nt][3] + bias.y);
        }
    }
}

// ---------------------------------------------------------------------------
extern "C" void kernel_launch(void* const* d_in, const int* in_sizes, int n_in,
                              void* d_out, int out_size)
{
    const float* X  = (const float*)d_in[0];
    const float* Wq = (const float*)d_in[1];
    const float* Wk = (const float*)d_in[2];
    const float* Wv = (const float*)d_in[3];
    const float* Wo = (const float*)d_in[4];
    const float* bo = (const float*)d_in[5];
    float* out = (float*)d_out;

    cvt_all<<<2048, 256>>>(X, Wq, Wk, Wv, Wo);
    proj_tc<<<dim3(24, 64), 256>>>();
    perm_kv<<<2048, 256>>>();
    attn_tc<<<dim3(16, 64), 256>>>();
    outproj_tc<<<dim3(8, 64), 256>>>(bo, out);
}